// round 16
// baseline (speedup 1.0000x reference)
#include <cuda_runtime.h>
#include <stdint.h>
#include <math.h>
#include <mma.h>
#include <cuda_bf16.h>

using namespace nvcuda;

#define B_SZ 16
#define D_MODEL 384
#define DEPTH 24
#define D_INNER 768
#define D_STATE 16
#define D_CONV 4
#define DT_RANK 24
#define N_CLASSES 1000
#define L_TOK 196
#define NTOK (B_SZ * L_TOK)            // 3136
#define NTOK_PAD 3200                  // multiple of 64
#define XPROJ_OUT (DT_RANK + 2 * D_STATE)  // 56

#define SQRT_C 0.70710678118654752f
#define MAX_NORM 1.3435028842544403f   // 0.95/sqrt(0.5)
#define C_CURV 0.5f

// ---------------- scratch (device globals; zero-init, no allocation) --------
__device__ float g_hidden [NTOK_PAD * D_MODEL];
__device__ float g_resid  [NTOK_PAD * D_MODEL];
__device__ float g_tmp    [NTOK_PAD * D_MODEL];
__device__ float g_xz     [NTOK_PAD * 2 * D_INNER];
__device__ float g_dbl    [NTOK_PAD * XPROJ_OUT];
__device__ float g_pool   [B_SZ * D_MODEL];
// bf16 GEMM operands
__device__ __nv_bfloat16 gh_patches[NTOK_PAD * 768];
__device__ __nv_bfloat16 gh_emb    [NTOK_PAD * D_MODEL];
__device__ __nv_bfloat16 gh_hn     [NTOK_PAD * D_MODEL];
__device__ __nv_bfloat16 gh_u      [NTOK_PAD * D_INNER];
__device__ __nv_bfloat16 gh_y      [NTOK_PAD * D_INNER];
// bf16 weights
__device__ __nv_bfloat16 gh_patch_w[D_MODEL * 768];
__device__ __nv_bfloat16 gh_hyp_w  [D_MODEL * D_MODEL];
__device__ __nv_bfloat16 gh_in_w   [DEPTH * 2 * D_INNER * D_MODEL];
__device__ __nv_bfloat16 gh_xp_w   [DEPTH * XPROJ_OUT * D_INNER];
__device__ __nv_bfloat16 gh_out_w  [DEPTH * D_MODEL * D_INNER];

// ---------------- helpers ---------------------------------------------------
__device__ __forceinline__ float warpSum(float v) {
    #pragma unroll
    for (int o = 16; o; o >>= 1) v += __shfl_xor_sync(0xffffffffu, v, o);
    return v;
}
__device__ __forceinline__ float fsigmoid(float x) { return 1.f / (1.f + __expf(-x)); }

__device__ __forceinline__ void cpasync16(void* smem_dst, const void* gsrc) {
    unsigned int s = (unsigned int)__cvta_generic_to_shared(smem_dst);
    asm volatile("cp.async.cg.shared.global [%0], [%1], 16;\n" :: "r"(s), "l"(gsrc));
}

// ---------------- fp32 -> bf16 conversion -----------------------------------
__global__ void k_f2h(const float* __restrict__ src, __nv_bfloat16* __restrict__ dst,
                      int n) {
    int i = blockIdx.x * blockDim.x + threadIdx.x;
    if (i < n) dst[i] = __float2bfloat16(src[i]);
}

// ---------------- im2col for patch embed (writes bf16) ----------------------
__global__ void k_im2col(const float* __restrict__ x) {
    int idx = blockIdx.x * blockDim.x + threadIdx.x;
    if (idx >= NTOK * 768) return;
    int col = idx % 768, row = idx / 768;
    int b = row / L_TOK, t = row % L_TOK;
    int ph = t / 14, pw = t % 14;
    int c = col >> 8, rem = col & 255, ii = rem >> 4, jj = rem & 15;
    gh_patches[idx] = __float2bfloat16(
        x[((b * 3 + c) * 224 + ph * 16 + ii) * 224 + pw * 16 + jj]);
}

// ---------------- double-buffered cp.async bf16 GEMM (R10-proven) -----------
// C[M,N] fp32 = A[M,K] @ W[N,K]^T (+bias). M mult 64, K mult 32.
// N mult 64 unless N_GUARD. BM=BN=64, BK=32, 128 thr, 4 warps, m16n16k16.
#define LDH 40
template<bool HAS_BIAS, bool N_GUARD>
__global__ __launch_bounds__(128) void k_gemm_bf(
    const __nv_bfloat16* __restrict__ A, const __nv_bfloat16* __restrict__ W,
    const float* __restrict__ bias, float* __restrict__ C,
    int M, int N, int K)
{
    constexpr int BM = 64, BN = 64, BK = 32;
    __shared__ float smf[5200];
    __nv_bfloat16* smh = (__nv_bfloat16*)smf;
    __nv_bfloat16* AsB = smh;
    __nv_bfloat16* BsB = smh + 2 * BM * LDH;

    const int tid = threadIdx.x;
    const int warp = tid >> 5, wm = warp >> 1, wn = warp & 1;
    const int row0 = blockIdx.y * BM, col0 = blockIdx.x * BN;

    wmma::fragment<wmma::accumulator, 16, 16, 16, float> acc[2][2];
    #pragma unroll
    for (int i = 0; i < 2; i++)
        #pragma unroll
        for (int j = 0; j < 2; j++) wmma::fill_fragment(acc[i][j], 0.f);

    const int nIt = K / BK;

    auto issue = [&](int buf, int k0) {
        #pragma unroll
        for (int i = 0; i < 2; i++) {
            int id = tid + i * 128;
            int r = id >> 2, c = (id & 3) * 8;
            cpasync16(&AsB[buf * BM * LDH + r * LDH + c],
                      &A[(size_t)(row0 + r) * K + k0 + c]);
        }
        #pragma unroll
        for (int i = 0; i < 2; i++) {
            int id = tid + i * 128;
            int r = id >> 2, c = (id & 3) * 8;
            if (!N_GUARD || (col0 + r) < N)
                cpasync16(&BsB[buf * BN * LDH + r * LDH + c],
                          &W[(size_t)(col0 + r) * K + k0 + c]);
        }
        asm volatile("cp.async.commit_group;\n" ::);
    };

    issue(0, 0);
    for (int it = 0; it < nIt; it++) {
        int buf = it & 1;
        if (it + 1 < nIt) {
            issue(buf ^ 1, (it + 1) * BK);
            asm volatile("cp.async.wait_group 1;\n" ::);
        } else {
            asm volatile("cp.async.wait_group 0;\n" ::);
        }
        __syncthreads();
        const __nv_bfloat16* As = &AsB[buf * BM * LDH];
        const __nv_bfloat16* Bs = &BsB[buf * BN * LDH];
        #pragma unroll
        for (int kk = 0; kk < BK; kk += 16) {
            wmma::fragment<wmma::matrix_a, 16, 16, 16, __nv_bfloat16, wmma::row_major> a[2];
            wmma::fragment<wmma::matrix_b, 16, 16, 16, __nv_bfloat16, wmma::col_major> b[2];
            #pragma unroll
            for (int i = 0; i < 2; i++)
                wmma::load_matrix_sync(a[i], &As[(wm * 32 + i * 16) * LDH + kk], LDH);
            #pragma unroll
            for (int j = 0; j < 2; j++)
                wmma::load_matrix_sync(b[j], &Bs[(wn * 32 + j * 16) * LDH + kk], LDH);
            #pragma unroll
            for (int i = 0; i < 2; i++)
                #pragma unroll
                for (int j = 0; j < 2; j++)
                    wmma::mma_sync(acc[i][j], a[i], b[j], acc[i][j]);
        }
        __syncthreads();
    }

    if (!HAS_BIAS && !N_GUARD) {
        #pragma unroll
        for (int i = 0; i < 2; i++)
            #pragma unroll
            for (int j = 0; j < 2; j++)
                wmma::store_matrix_sync(
                    &C[(size_t)(row0 + wm * 32 + i * 16) * N + col0 + wn * 32 + j * 16],
                    acc[i][j], N, wmma::mem_row_major);
    } else {
        __syncthreads();
        #pragma unroll
        for (int i = 0; i < 2; i++)
            #pragma unroll
            for (int j = 0; j < 2; j++)
                wmma::store_matrix_sync(&smf[(wm * 32 + i * 16) * 68 + wn * 32 + j * 16],
                                        acc[i][j], 68, wmma::mem_row_major);
        __syncthreads();
        for (int idx = tid; idx < BM * BN; idx += 128) {
            int m = idx >> 6, n = idx & 63;
            if (N_GUARD && (col0 + n) >= N) continue;
            float v = smf[m * 68 + n];
            if (HAS_BIAS) v += bias[col0 + n];
            C[(size_t)(row0 + m) * N + col0 + n] = v;
        }
    }
}

// ---------------- depthwise causal conv + silu (bf16 out only) --------------
__global__ void k_conv_silu(const float* __restrict__ xz, const float* __restrict__ cw,
                            const float* __restrict__ cb) {
    int idx = blockIdx.x * blockDim.x + threadIdx.x;
    if (idx >= NTOK * D_INNER) return;
    int d = idx % D_INNER, bt = idx / D_INNER;
    int l = bt % L_TOK;
    float acc = cb[d];
    #pragma unroll
    for (int k = 0; k < D_CONV; k++) {
        int l2 = l + k - (D_CONV - 1);
        if (l2 >= 0) acc += cw[d * D_CONV + k] * xz[(size_t)(bt + l2 - l) * (2 * D_INNER) + d];
    }
    float uv = acc * fsigmoid(acc);
    gh_u[idx] = __float2bfloat16(uv);
}

// ---------------- scan v3: chunked smem stage + fused dtproj -----------------
// Block = 512 threads; one batch b, 32 channels d. Chunks of 14 timesteps.
// Phase 1: coalesced load of dbl/u/z chunk. Phase 2: 448 threads (warp=step,
// lane=d) compute dt = softplus(dbl[:24]*dtw + b) with dtw in registers.
// Phase 3: 32 groups x 16 state-lanes run 14 recurrence steps from smem,
// buffering y. Phase 4: coalesced bf16 y writeback. 3 barriers per chunk.
#define SCH 14
__global__ __launch_bounds__(512) void k_scan(
    const float* __restrict__ dbl, const float* __restrict__ xz,
    const float* __restrict__ dtw, const float* __restrict__ dtb,
    const float* __restrict__ A_log, const float* __restrict__ Dp)
{
    const int b = blockIdx.y, d0 = blockIdx.x * 32;
    const int tid = threadIdx.x;
    const int g = tid >> 4, s = tid & 15;

    __shared__ float sdbl[SCH][XPROJ_OUT];
    __shared__ float sdt [SCH][32];
    __shared__ float su  [SCH][32];
    __shared__ float sz  [SCH][32];
    __shared__ float sy  [SCH][32];

    // recurrence constants (per 16-lane group)
    const float a  = -expf(A_log[(d0 + g) * D_STATE + s]);
    const float Dv = Dp[d0 + g];
    // dt constants (per (step,lane) thread, lane<->d fixed across chunks)
    const int dtStep = tid >> 5, dtD = tid & 31;   // warp = step, lane = d
    float w[DT_RANK]; float bsf = 0.f;
    if (tid < SCH * 32) {
        #pragma unroll
        for (int r = 0; r < DT_RANK; r++) w[r] = dtw[(d0 + dtD) * DT_RANK + r];
        bsf = dtb[d0 + dtD];
    }

    float h = 0.f;
    const int base0 = b * L_TOK;

    for (int c = 0; c < L_TOK / SCH; c++) {
        const int r0 = base0 + c * SCH;
        // phase 1: loads (coalesced)
        for (int idx = tid; idx < SCH * XPROJ_OUT; idx += 512) {
            int row = idx / XPROJ_OUT, col = idx % XPROJ_OUT;
            sdbl[row][col] = dbl[(size_t)(r0 + row) * XPROJ_OUT + col];
        }
        if (tid < SCH * 32) {
            int row = tid >> 5, dd = tid & 31;
            su[row][dd] = __bfloat162float(gh_u[(size_t)(r0 + row) * D_INNER + d0 + dd]);
            sz[row][dd] = xz[(size_t)(r0 + row) * (2 * D_INNER) + D_INNER + d0 + dd];
        }
        __syncthreads();
        // phase 2: dt (smem-broadcast dbl reads, registers for weights)
        if (tid < SCH * 32) {
            float dot = bsf;
            #pragma unroll
            for (int r = 0; r < DT_RANK; r++) dot += sdbl[dtStep][r] * w[r];
            sdt[dtStep][dtD] = (dot > 20.f) ? dot : log1pf(__expf(dot));
        }
        __syncthreads();
        // phase 3: recurrence
        #pragma unroll
        for (int t = 0; t < SCH; t++) {
            float dtv = sdt[t][g];
            float uv  = su[t][g];
            float Bv  = sdbl[t][DT_RANK + s];
            float Cv  = sdbl[t][DT_RANK + D_STATE + s];
            h = __expf(dtv * a) * h + dtv * Bv * uv;
            float p = h * Cv;
            p += __shfl_down_sync(0xffffffffu, p, 8, 16);
            p += __shfl_down_sync(0xffffffffu, p, 4, 16);
            p += __shfl_down_sync(0xffffffffu, p, 2, 16);
            p += __shfl_down_sync(0xffffffffu, p, 1, 16);
            if (s == 0) {
                float zv = sz[t][g];
                sy[t][g] = (p + Dv * uv) * zv * fsigmoid(zv);
            }
        }
        __syncthreads();
        // phase 4: coalesced y writeback
        if (tid < SCH * 32) {
            int row = tid >> 5, dd = tid & 31;
            gh_y[(size_t)(r0 + row) * D_INNER + d0 + dd] = __float2bfloat16(sy[row][dd]);
        }
        // barrier at top of next chunk's phase-2 protects smem reuse
        __syncthreads();
    }
}

// ---------------- warp-per-row hyperbolic kernels ---------------------------
#define ROWS_PER_BLK 8

__global__ void k_expmap_rows(const float* __restrict__ in, float* __restrict__ out,
                              __nv_bfloat16* __restrict__ outh, int nrows) {
    int row = blockIdx.x * ROWS_PER_BLK + (threadIdx.x >> 5);
    if (row >= nrows) return;
    int lane = threadIdx.x & 31;
    float v[12]; float s2 = 0.f;
    #pragma unroll
    for (int j = 0; j < 12; j++) { v[j] = in[row * D_MODEL + lane + j * 32]; s2 += v[j] * v[j]; }
    s2 = warpSum(s2);
    float n = sqrtf(s2 + 1e-15f);
    n = fminf(fmaxf(n, 1e-8f), 5.0f);
    float coef = tanhf(SQRT_C * n) / (SQRT_C * n);
    float rn = sqrtf(coef * coef * s2 + 1e-15f);
    float scale = (rn > MAX_NORM) ? (MAX_NORM / rn) : 1.f;
    #pragma unroll
    for (int j = 0; j < 12; j++) {
        float r = coef * v[j] * scale;
        out[row * D_MODEL + lane + j * 32] = r;
        if (outh) outh[row * D_MODEL + lane + j * 32] = __float2bfloat16(r);
    }
}

__global__ void k_logmap_rows(const float* __restrict__ in, float* __restrict__ out,
                              int nrows) {
    int row = blockIdx.x * ROWS_PER_BLK + (threadIdx.x >> 5);
    if (row >= nrows) return;
    int lane = threadIdx.x & 31;
    float v[12]; float s2 = 0.f;
    #pragma unroll
    for (int j = 0; j < 12; j++) { v[j] = in[row * D_MODEL + lane + j * 32]; s2 += v[j] * v[j]; }
    s2 = warpSum(s2);
    float n = sqrtf(s2 + 1e-15f);
    n = fminf(fmaxf(n, 1e-8f), MAX_NORM);
    float coef = atanhf(fminf(SQRT_C * n, 0.95f)) / (SQRT_C * n);
    #pragma unroll
    for (int j = 0; j < 12; j++) out[row * D_MODEL + lane + j * 32] = coef * v[j];
}

__global__ void k_mobius(const float* __restrict__ h, const float* __restrict__ mx,
                         const float* __restrict__ hb, float* __restrict__ out) {
    int row = blockIdx.x * ROWS_PER_BLK + (threadIdx.x >> 5);
    if (row >= NTOK) return;
    int lane = threadIdx.x & 31;
    float hv[12], mv[12], bv[12];
    float sh2 = 0.f, smx2 = 0.f, y2 = 0.f;
    #pragma unroll
    for (int j = 0; j < 12; j++) {
        int e = lane + j * 32;
        hv[j] = h[row * D_MODEL + e]; mv[j] = mx[row * D_MODEL + e]; bv[j] = hb[e];
        sh2 += hv[j] * hv[j]; smx2 += mv[j] * mv[j]; y2 += bv[j] * bv[j];
    }
    sh2 = warpSum(sh2); smx2 = warpSum(smx2); y2 = warpSum(y2);
    float xn  = fmaxf(sqrtf(sh2 + 1e-15f), 1e-8f);
    float mxn = fmaxf(sqrtf(smx2 + 1e-15f), 1e-8f);
    float tt = tanhf(mxn / xn * atanhf(fminf(SQRT_C * xn, 1.f - 1e-5f)));
    float c1 = tt / (mxn * SQRT_C);
    float xy = 0.f;
    #pragma unroll
    for (int j = 0; j < 12; j++) xy += c1 * mv[j] * bv[j];
    xy = warpSum(xy);
    float x2 = c1 * c1 * smx2;
    float alpha = 1.f + 2.f * C_CURV * xy + C_CURV * y2;
    float beta_ = 1.f - C_CURV * x2;
    float den = fmaxf(1.f + 2.f * C_CURV * xy + C_CURV * C_CURV * x2 * y2, 1e-15f);
    float rden = 1.f / den;
    #pragma unroll
    for (int j = 0; j < 12; j++)
        out[row * D_MODEL + lane + j * 32] = (alpha * c1 * mv[j] + beta_ * bv[j]) * rden;
}

__global__ void k_resid_hyp_ln(const float* __restrict__ hidden,
                               float* __restrict__ resid,
                               const float* __restrict__ gamma,
                               const float* __restrict__ beta,
                               __nv_bfloat16* __restrict__ outh,
                               float* __restrict__ outf, int doAdd) {
    int row = blockIdx.x * ROWS_PER_BLK + (threadIdx.x >> 5);
    if (row >= NTOK) return;
    int lane = threadIdx.x & 31;
    float v[12]; float s2 = 0.f;
    #pragma unroll
    for (int j = 0; j < 12; j++) {
        int e = lane + j * 32;
        float x = hidden[row * D_MODEL + e];
        if (doAdd) x += resid[row * D_MODEL + e];
        resid[row * D_MODEL + e] = x;
        v[j] = x; s2 += x * x;
    }
    s2 = warpSum(s2);
    float n = sqrtf(s2 + 1e-15f);
    n = fminf(fmaxf(n, 1e-8f), MAX_NORM);
    float coef = atanhf(fminf(SQRT_C * n, 0.95f)) / (SQRT_C * n);
    float mean = 0.f;
    #pragma unroll
    for (int j = 0; j < 12; j++) { v[j] *= coef; mean += v[j]; }
    mean = warpSum(mean) * (1.f / D_MODEL);
    float var = 0.f;
    #pragma unroll
    for (int j = 0; j < 12; j++) { v[j] -= mean; var += v[j] * v[j]; }
    var = warpSum(var) * (1.f / (D_MODEL - 1));
    float rstd = 1.f / (sqrtf(var) + 1e-5f);
    float su2 = 0.f;
    #pragma unroll
    for (int j = 0; j < 12; j++) {
        int e = lane + j * 32;
        v[j] = v[j] * rstd * gamma[e] + beta[e];
        su2 += v[j] * v[j];
    }
    su2 = warpSum(su2);
    float nu = sqrtf(su2 + 1e-15f);
    nu = fminf(fmaxf(nu, 1e-8f), 5.0f);
    float ec = tanhf(SQRT_C * nu) / (SQRT_C * nu);
    float rn = sqrtf(ec * ec * su2 + 1e-15f);
    float scale = (rn > MAX_NORM) ? (MAX_NORM / rn) : 1.f;
    #pragma unroll
    for (int j = 0; j < 12; j++) {
        float r = ec * v[j] * scale;
        if (outh) outh[row * D_MODEL + lane + j * 32] = __float2bfloat16(r);
        if (outf) outf[row * D_MODEL + lane + j * 32] = r;
    }
}

__global__ void k_posemb(const float* __restrict__ in, const float* __restrict__ pos,
                         float* __restrict__ out) {
    int row = blockIdx.x * ROWS_PER_BLK + (threadIdx.x >> 5);
    if (row >= NTOK) return;
    int lane = threadIdx.x & 31;
    int t = row % L_TOK;
    float v[12]; float s2 = 0.f;
    #pragma unroll
    for (int j = 0; j < 12; j++) { v[j] = in[row * D_MODEL + lane + j * 32]; s2 += v[j] * v[j]; }
    s2 = warpSum(s2);
    float n = sqrtf(s2 + 1e-15f);
    n = fminf(fmaxf(n, 1e-8f), MAX_NORM);
    float coef = atanhf(fminf(SQRT_C * n, 0.95f)) / (SQRT_C * n);
    float su2 = 0.f;
    #pragma unroll
    for (int j = 0; j < 12; j++) {
        int e = lane + j * 32;
        v[j] = coef * v[j] + pos[t * D_MODEL + e];
        su2 += v[j] * v[j];
    }
    su2 = warpSum(su2);
    float nu = sqrtf(su2 + 1e-15f);
    nu = fminf(fmaxf(nu, 1e-8f), 5.0f);
    float ec = tanhf(SQRT_C * nu) / (SQRT_C * nu);
    float rn = sqrtf(ec * ec * su2 + 1e-15f);
    float scale = (rn > MAX_NORM) ? (MAX_NORM / rn) : 1.f;
    #pragma unroll
    for (int j = 0; j < 12; j++) out[row * D_MODEL + lane + j * 32] = ec * v[j] * scale;
}

// ---------------- mean pool over tokens -------------------------------------
__global__ void k_pool(const float* __restrict__ in, float* __restrict__ out) {
    int b = blockIdx.x, e = threadIdx.x;
    float s = 0.f;
    for (int t = 0; t < L_TOK; t++) s += in[(b * L_TOK + t) * D_MODEL + e];
    out[b * D_MODEL + e] = s * (1.f / L_TOK);
}

// ---------------- hyperbolic distance classifier ----------------------------
__global__ void k_classifier(const float* __restrict__ pooled,
                             const float* __restrict__ protos,
                             float* __restrict__ out) {
    int warp = (blockIdx.x * blockDim.x + threadIdx.x) >> 5;
    int lane = threadIdx.x & 31;
    if (warp >= B_SZ * N_CLASSES) return;
    int b = warp / N_CLASSES, c = warp % N_CLASSES;
    float s_ab = 0.f, s_aa = 0.f, s_bb = 0.f;
    for (int e = lane; e < D_MODEL; e += 32) {
        float pa = pooled[b * D_MODEL + e];
        float pr = protos[c * D_MODEL + e];
        s_ab += pa * pr; s_aa += pa * pa; s_bb += pr * pr;
    }
    #pragma unroll
    for (int o = 16; o; o >>= 1) {
        s_ab += __shfl_down_sync(0xffffffffu, s_ab, o);
        s_aa += __shfl_down_sync(0xffffffffu, s_aa, o);
        s_bb += __shfl_down_sync(0xffffffffu, s_bb, o);
    }
    if (lane == 0) {
        float xy = -s_ab;
        float x2 = s_aa, y2 = s_bb;
        float alpha = 1.f + 2.f * C_CURV * xy + C_CURV * y2;
        float beta_ = 1.f - C_CURV * x2;
        float num2 = alpha * alpha * x2 + 2.f * alpha * beta_ * xy + beta_ * beta_ * y2;
        float den = fmaxf(1.f + 2.f * C_CURV * xy + C_CURV * C_CURV * x2 * y2, 1e-15f);
        float nrm = sqrtf(fmaxf(num2, 0.f) / (den * den) + 1e-15f);
        float dn = fminf(SQRT_C * nrm, 1.f - 1e-5f);
        out[b * N_CLASSES + c] = -(2.f / SQRT_C) * atanhf(dn);
    }
}

// ---------------- host orchestration ----------------------------------------
static void f2h(const float* src, __nv_bfloat16* dst, int n) {
    k_f2h<<<(n + 255) / 256, 256>>>(src, dst, n);
}
static void gemm(const __nv_bfloat16* A, const __nv_bfloat16* W, const float* bias,
                 float* C, int N, int K) {
    dim3 grid(N / 64, NTOK_PAD / 64);
    if (bias) k_gemm_bf<true, false><<<grid, 128>>>(A, W, bias, C, NTOK_PAD, N, K);
    else      k_gemm_bf<false, false><<<grid, 128>>>(A, W, nullptr, C, NTOK_PAD, N, K);
}
static void gemm_ng(const __nv_bfloat16* A, const __nv_bfloat16* W, float* C,
                    int N, int K) {
    dim3 grid((N + 63) / 64, NTOK_PAD / 64);
    k_gemm_bf<false, true><<<grid, 128>>>(A, W, nullptr, C, NTOK_PAD, N, K);
}

#define ROW_GRID ((NTOK + ROWS_PER_BLK - 1) / ROWS_PER_BLK)

extern "C" void kernel_launch(void* const* d_in, const int* in_sizes, int n_in,
                              void* d_out, int out_size) {
    const float* x        = (const float*)d_in[0];
    const float* patch_w  = (const float*)d_in[1];
    const float* patch_b  = (const float*)d_in[2];
    const float* hyp_w    = (const float*)d_in[3];
    const float* hyp_b    = (const float*)d_in[4];
    const float* pe_gamma = (const float*)d_in[5];
    const float* pe_beta  = (const float*)d_in[6];
    const float* pos_emb  = (const float*)d_in[7];
    const float* in_proj  = (const float*)d_in[8];
    const float* conv_w   = (const float*)d_in[9];
    const float* conv_b   = (const float*)d_in[10];
    const float* x_proj   = (const float*)d_in[11];
    const float* dt_w     = (const float*)d_in[12];
    const float* dt_b     = (const float*)d_in[13];
    const float* A_log    = (const float*)d_in[14];
    const float* Dp       = (const float*)d_in[15];
    const float* out_proj = (const float*)d_in[16];
    const float* gamma    = (const float*)d_in[17];
    const float* beta     = (const float*)d_in[18];
    const float* gamma_f  = (const float*)d_in[19];
    const float* beta_f   = (const float*)d_in[20];
    const float* protos   = (const float*)d_in[21];
    float* out = (float*)d_out;

    float *hidden, *resid, *tmp, *xz, *dbl, *pool;
    cudaGetSymbolAddress((void**)&hidden,  g_hidden);
    cudaGetSymbolAddress((void**)&resid,   g_resid);
    cudaGetSymbolAddress((void**)&tmp,     g_tmp);
    cudaGetSymbolAddress((void**)&xz,      g_xz);
    cudaGetSymbolAddress((void**)&dbl,     g_dbl);
    cudaGetSymbolAddress((void**)&pool,    g_pool);
    __nv_bfloat16 *h_patches, *h_emb, *h_hn, *h_u, *h_y;
    __nv_bfloat16 *h_patch_w, *h_hyp_w, *h_in_w, *h_xp_w, *h_out_w;
    cudaGetSymbolAddress((void**)&h_patches, gh_patches);
    cudaGetSymbolAddress((void**)&h_emb,     gh_emb);
    cudaGetSymbolAddress((void**)&h_hn,      gh_hn);
    cudaGetSymbolAddress((void**)&h_u,       gh_u);
    cudaGetSymbolAddress((void**)&h_y,       gh_y);
    cudaGetSymbolAddress((void**)&h_patch_w, gh_patch_w);
    cudaGetSymbolAddress((void**)&h_hyp_w,   gh_hyp_w);
    cudaGetSymbolAddress((void**)&h_in_w,    gh_in_w);
    cudaGetSymbolAddress((void**)&h_xp_w,    gh_xp_w);
    cudaGetSymbolAddress((void**)&h_out_w,   gh_out_w);

    // weight conversion (every launch; deterministic)
    f2h(patch_w,  h_patch_w, D_MODEL * 768);
    f2h(hyp_w,    h_hyp_w,   D_MODEL * D_MODEL);
    f2h(in_proj,  h_in_w,    DEPTH * 2 * D_INNER * D_MODEL);
    f2h(x_proj,   h_xp_w,    DEPTH * XPROJ_OUT * D_INNER);
    f2h(out_proj, h_out_w,   DEPTH * D_MODEL * D_INNER);

    // patch embed -> tokens
    k_im2col<<<(NTOK * 768 + 255) / 256, 256>>>(x);
    gemm(h_patches, h_patch_w, patch_b, hidden, D_MODEL, 768);
    // hyperbolic embedding
    k_expmap_rows<<<ROW_GRID, 256>>>(hidden, hidden, h_emb, NTOK);
    gemm(h_emb, h_hyp_w, nullptr, tmp, D_MODEL, D_MODEL);
    k_mobius<<<ROW_GRID, 256>>>(hidden, tmp, hyp_b, hidden);
    k_resid_hyp_ln<<<ROW_GRID, 256>>>(hidden, tmp, pe_gamma, pe_beta,
                                      nullptr, hidden, 0);
    k_posemb<<<ROW_GRID, 256>>>(hidden, pos_emb, hidden);

    for (int i = 0; i < DEPTH; i++) {
        k_resid_hyp_ln<<<ROW_GRID, 256>>>(hidden, resid,
                                          gamma + i * D_MODEL, beta + i * D_MODEL,
                                          h_hn, nullptr, i > 0);
        gemm(h_hn, h_in_w + (size_t)i * 2 * D_INNER * D_MODEL, nullptr, xz,
             2 * D_INNER, D_MODEL);
        k_conv_silu<<<(NTOK * D_INNER + 255) / 256, 256>>>(
            xz, conv_w + i * D_INNER * D_CONV, conv_b + i * D_INNER);
        gemm_ng(h_u, h_xp_w + (size_t)i * XPROJ_OUT * D_INNER, dbl,
                XPROJ_OUT, D_INNER);
        k_scan<<<dim3(D_INNER / 32, B_SZ), 512>>>(
            dbl, xz, dt_w + (size_t)i * D_INNER * DT_RANK, dt_b + i * D_INNER,
            A_log + (size_t)i * D_INNER * D_STATE, Dp + i * D_INNER);
        gemm(h_y, h_out_w + (size_t)i * D_MODEL * D_INNER, nullptr, hidden,
             D_MODEL, D_INNER);
    }

    // final residual + LN + pool + classify
    k_resid_hyp_ln<<<ROW_GRID, 256>>>(hidden, resid, gamma_f, beta_f,
                                      nullptr, tmp, 1);
    k_logmap_rows<<<ROW_GRID, 256>>>(tmp, tmp, NTOK);
    k_pool<<<B_SZ, D_MODEL>>>(tmp, pool);
    k_expmap_rows<<<(B_SZ + ROWS_PER_BLK - 1) / ROWS_PER_BLK, 256>>>(
        pool, pool, nullptr, B_SZ);
    k_classifier<<<(B_SZ * N_CLASSES * 32 + 255) / 256, 256>>>(pool, protos, out);
}

// round 17
// speedup vs baseline: 1.2793x; 1.2793x over previous
#include <cuda_runtime.h>
#include <stdint.h>
#include <math.h>
#include <mma.h>
#include <cuda_bf16.h>

using namespace nvcuda;

#define B_SZ 16
#define D_MODEL 384
#define DEPTH 24
#define D_INNER 768
#define D_STATE 16
#define D_CONV 4
#define DT_RANK 24
#define N_CLASSES 1000
#define L_TOK 196
#define NTOK (B_SZ * L_TOK)            // 3136
#define NTOK_PAD 3200                  // multiple of 64
#define XPROJ_OUT (DT_RANK + 2 * D_STATE)  // 56

#define SQRT_C 0.70710678118654752f
#define MAX_NORM 1.3435028842544403f   // 0.95/sqrt(0.5)
#define C_CURV 0.5f

// ---------------- scratch (device globals; zero-init, no allocation) --------
__device__ float g_hidden [NTOK_PAD * D_MODEL];
__device__ float g_resid  [NTOK_PAD * D_MODEL];
__device__ float g_tmp    [NTOK_PAD * D_MODEL];
__device__ float g_xz     [NTOK_PAD * 2 * D_INNER];
__device__ float g_dbl    [NTOK_PAD * XPROJ_OUT];
__device__ float g_dt     [NTOK_PAD * D_INNER];
__device__ float g_pool   [B_SZ * D_MODEL];
// bf16 GEMM operands
__device__ __nv_bfloat16 gh_patches[NTOK_PAD * 768];
__device__ __nv_bfloat16 gh_emb    [NTOK_PAD * D_MODEL];
__device__ __nv_bfloat16 gh_hn     [NTOK_PAD * D_MODEL];
__device__ __nv_bfloat16 gh_u      [NTOK_PAD * D_INNER];
__device__ __nv_bfloat16 gh_y      [NTOK_PAD * D_INNER];
// bf16 weights
__device__ __nv_bfloat16 gh_patch_w[D_MODEL * 768];
__device__ __nv_bfloat16 gh_hyp_w  [D_MODEL * D_MODEL];
__device__ __nv_bfloat16 gh_in_w   [DEPTH * 2 * D_INNER * D_MODEL];
__device__ __nv_bfloat16 gh_xp_w   [DEPTH * XPROJ_OUT * D_INNER];
__device__ __nv_bfloat16 gh_out_w  [DEPTH * D_MODEL * D_INNER];

// ---------------- helpers ---------------------------------------------------
__device__ __forceinline__ float warpSum(float v) {
    #pragma unroll
    for (int o = 16; o; o >>= 1) v += __shfl_xor_sync(0xffffffffu, v, o);
    return v;
}
__device__ __forceinline__ float fsigmoid(float x) { return 1.f / (1.f + __expf(-x)); }

__device__ __forceinline__ void cpasync16(void* smem_dst, const void* gsrc) {
    unsigned int s = (unsigned int)__cvta_generic_to_shared(smem_dst);
    asm volatile("cp.async.cg.shared.global [%0], [%1], 16;\n" :: "r"(s), "l"(gsrc));
}

// ---------------- fp32 -> bf16 conversion (vectorized: 4 elems/thread) ------
__global__ void k_f2h4(const float* __restrict__ src, __nv_bfloat16* __restrict__ dst,
                       int n4) {
    int i = blockIdx.x * blockDim.x + threadIdx.x;
    if (i >= n4) return;
    float4 v = __ldg(&((const float4*)src)[i]);
    __nv_bfloat162 lo = __floats2bfloat162_rn(v.x, v.y);
    __nv_bfloat162 hi = __floats2bfloat162_rn(v.z, v.w);
    ((__nv_bfloat162*)dst)[i * 2 + 0] = lo;
    ((__nv_bfloat162*)dst)[i * 2 + 1] = hi;
}

// ---------------- im2col for patch embed (writes bf16) ----------------------
__global__ void k_im2col(const float* __restrict__ x) {
    int idx = blockIdx.x * blockDim.x + threadIdx.x;
    if (idx >= NTOK * 768) return;
    int col = idx % 768, row = idx / 768;
    int b = row / L_TOK, t = row % L_TOK;
    int ph = t / 14, pw = t % 14;
    int c = col >> 8, rem = col & 255, ii = rem >> 4, jj = rem & 15;
    gh_patches[idx] = __float2bfloat16(
        x[((b * 3 + c) * 224 + ph * 16 + ii) * 224 + pw * 16 + jj]);
}

// ---------------- double-buffered cp.async bf16 GEMM (R10-proven) -----------
// C[M,N] fp32 = A[M,K] @ W[N,K]^T (+bias). M mult 64, K mult 32.
// N mult 64 unless N_GUARD. BM=BN=64, BK=32, 128 thr, 4 warps, m16n16k16.
#define LDH 40
template<bool HAS_BIAS, bool N_GUARD>
__global__ __launch_bounds__(128) void k_gemm_bf(
    const __nv_bfloat16* __restrict__ A, const __nv_bfloat16* __restrict__ W,
    const float* __restrict__ bias, float* __restrict__ C,
    int M, int N, int K)
{
    constexpr int BM = 64, BN = 64, BK = 32;
    __shared__ float smf[5200];
    __nv_bfloat16* smh = (__nv_bfloat16*)smf;
    __nv_bfloat16* AsB = smh;
    __nv_bfloat16* BsB = smh + 2 * BM * LDH;

    const int tid = threadIdx.x;
    const int warp = tid >> 5, wm = warp >> 1, wn = warp & 1;
    const int row0 = blockIdx.y * BM, col0 = blockIdx.x * BN;

    wmma::fragment<wmma::accumulator, 16, 16, 16, float> acc[2][2];
    #pragma unroll
    for (int i = 0; i < 2; i++)
        #pragma unroll
        for (int j = 0; j < 2; j++) wmma::fill_fragment(acc[i][j], 0.f);

    const int nIt = K / BK;

    auto issue = [&](int buf, int k0) {
        #pragma unroll
        for (int i = 0; i < 2; i++) {
            int id = tid + i * 128;
            int r = id >> 2, c = (id & 3) * 8;
            cpasync16(&AsB[buf * BM * LDH + r * LDH + c],
                      &A[(size_t)(row0 + r) * K + k0 + c]);
        }
        #pragma unroll
        for (int i = 0; i < 2; i++) {
            int id = tid + i * 128;
            int r = id >> 2, c = (id & 3) * 8;
            if (!N_GUARD || (col0 + r) < N)
                cpasync16(&BsB[buf * BN * LDH + r * LDH + c],
                          &W[(size_t)(col0 + r) * K + k0 + c]);
        }
        asm volatile("cp.async.commit_group;\n" ::);
    };

    issue(0, 0);
    for (int it = 0; it < nIt; it++) {
        int buf = it & 1;
        if (it + 1 < nIt) {
            issue(buf ^ 1, (it + 1) * BK);
            asm volatile("cp.async.wait_group 1;\n" ::);
        } else {
            asm volatile("cp.async.wait_group 0;\n" ::);
        }
        __syncthreads();
        const __nv_bfloat16* As = &AsB[buf * BM * LDH];
        const __nv_bfloat16* Bs = &BsB[buf * BN * LDH];
        #pragma unroll
        for (int kk = 0; kk < BK; kk += 16) {
            wmma::fragment<wmma::matrix_a, 16, 16, 16, __nv_bfloat16, wmma::row_major> a[2];
            wmma::fragment<wmma::matrix_b, 16, 16, 16, __nv_bfloat16, wmma::col_major> b[2];
            #pragma unroll
            for (int i = 0; i < 2; i++)
                wmma::load_matrix_sync(a[i], &As[(wm * 32 + i * 16) * LDH + kk], LDH);
            #pragma unroll
            for (int j = 0; j < 2; j++)
                wmma::load_matrix_sync(b[j], &Bs[(wn * 32 + j * 16) * LDH + kk], LDH);
            #pragma unroll
            for (int i = 0; i < 2; i++)
                #pragma unroll
                for (int j = 0; j < 2; j++)
                    wmma::mma_sync(acc[i][j], a[i], b[j], acc[i][j]);
        }
        __syncthreads();
    }

    if (!HAS_BIAS && !N_GUARD) {
        #pragma unroll
        for (int i = 0; i < 2; i++)
            #pragma unroll
            for (int j = 0; j < 2; j++)
                wmma::store_matrix_sync(
                    &C[(size_t)(row0 + wm * 32 + i * 16) * N + col0 + wn * 32 + j * 16],
                    acc[i][j], N, wmma::mem_row_major);
    } else {
        __syncthreads();
        #pragma unroll
        for (int i = 0; i < 2; i++)
            #pragma unroll
            for (int j = 0; j < 2; j++)
                wmma::store_matrix_sync(&smf[(wm * 32 + i * 16) * 68 + wn * 32 + j * 16],
                                        acc[i][j], 68, wmma::mem_row_major);
        __syncthreads();
        for (int idx = tid; idx < BM * BN; idx += 128) {
            int m = idx >> 6, n = idx & 63;
            if (N_GUARD && (col0 + n) >= N) continue;
            float v = smf[m * 68 + n];
            if (HAS_BIAS) v += bias[col0 + n];
            C[(size_t)(row0 + m) * N + col0 + n] = v;
        }
    }
}

// ---------------- depthwise causal conv + silu (bf16 out only) --------------
__global__ void k_conv_silu(const float* __restrict__ xz, const float* __restrict__ cw,
                            const float* __restrict__ cb) {
    int idx = blockIdx.x * blockDim.x + threadIdx.x;
    if (idx >= NTOK * D_INNER) return;
    int d = idx % D_INNER, bt = idx / D_INNER;
    int l = bt % L_TOK;
    float acc = cb[d];
    #pragma unroll
    for (int k = 0; k < D_CONV; k++) {
        int l2 = l + k - (D_CONV - 1);
        if (l2 >= 0) acc += cw[d * D_CONV + k] * xz[(size_t)(bt + l2 - l) * (2 * D_INNER) + d];
    }
    float uv = acc * fsigmoid(acc);
    gh_u[idx] = __float2bfloat16(uv);
}

// ---------------- dt projection + softplus ----------------------------------
__global__ void k_dtproj(const float* __restrict__ dbl, const float* __restrict__ dtw,
                         const float* __restrict__ dtb, float* __restrict__ dt) {
    int idx = blockIdx.x * blockDim.x + threadIdx.x;
    if (idx >= NTOK * D_INNER) return;
    int d = idx % D_INNER, bt = idx / D_INNER;
    float acc = dtb[d];
    #pragma unroll
    for (int r = 0; r < DT_RANK; r++)
        acc += dbl[(size_t)bt * XPROJ_OUT + r] * dtw[d * DT_RANK + r];
    dt[idx] = (acc > 20.f) ? acc : log1pf(__expf(acc));
}

// ---------------- selective scan v2: smem-staged per-timestep (R12-proven) --
// Block = 512 threads = 32 groups x 16 state-lanes, one batch b, 32 d's.
// Per t, one cooperative load of (dbl row, dt, u, z) into double-buffered smem.
__global__ __launch_bounds__(512) void k_scan(
    const float* __restrict__ dt, const float* __restrict__ dbl,
    const float* __restrict__ xz,
    const float* __restrict__ A_log, const float* __restrict__ Dp)
{
    const int b = blockIdx.y, d0 = blockIdx.x * 32;
    const int tid = threadIdx.x;
    const int g = tid >> 4, s = tid & 15;
    const int d = d0 + g;

    __shared__ float sdbl[2][64];
    __shared__ float sdt [2][32];
    __shared__ float su  [2][32];
    __shared__ float sz  [2][32];

    const float a  = -expf(A_log[d * D_STATE + s]);
    const float Dv = Dp[d];
    float h = 0.f;
    const int base0 = b * L_TOK;

    auto load = [&](int t, int buf) {
        int bt = base0 + t;
        if (tid < 56) {
            sdbl[buf][tid] = dbl[(size_t)bt * XPROJ_OUT + tid];
        } else if (tid >= 64 && tid < 96) {
            int i = tid - 64;
            sdt[buf][i] = dt[(size_t)bt * D_INNER + d0 + i];
        } else if (tid >= 96 && tid < 128) {
            int i = tid - 96;
            su[buf][i] = __bfloat162float(gh_u[(size_t)bt * D_INNER + d0 + i]);
        } else if (tid >= 128 && tid < 160) {
            int i = tid - 128;
            sz[buf][i] = xz[(size_t)bt * (2 * D_INNER) + D_INNER + d0 + i];
        }
    };

    load(0, 0);
    __syncthreads();
    for (int t = 0; t < L_TOK; t++) {
        int buf = t & 1;
        if (t + 1 < L_TOK) load(t + 1, buf ^ 1);
        float dtv = sdt[buf][g];
        float uv  = su[buf][g];
        float Bv  = sdbl[buf][DT_RANK + s];
        float Cv  = sdbl[buf][DT_RANK + D_STATE + s];
        h = __expf(dtv * a) * h + dtv * Bv * uv;
        float p = h * Cv;
        p += __shfl_down_sync(0xffffffffu, p, 8, 16);
        p += __shfl_down_sync(0xffffffffu, p, 4, 16);
        p += __shfl_down_sync(0xffffffffu, p, 2, 16);
        p += __shfl_down_sync(0xffffffffu, p, 1, 16);
        if (s == 0) {
            float zv = sz[buf][g];
            float yy = (p + Dv * uv) * zv * fsigmoid(zv);
            gh_y[(size_t)(base0 + t) * D_INNER + d] = __float2bfloat16(yy);
        }
        __syncthreads();
    }
}

// ---------------- warp-per-row hyperbolic kernels ---------------------------
#define ROWS_PER_BLK 8

__global__ void k_expmap_rows(const float* __restrict__ in, float* __restrict__ out,
                              __nv_bfloat16* __restrict__ outh, int nrows) {
    int row = blockIdx.x * ROWS_PER_BLK + (threadIdx.x >> 5);
    if (row >= nrows) return;
    int lane = threadIdx.x & 31;
    float v[12]; float s2 = 0.f;
    #pragma unroll
    for (int j = 0; j < 12; j++) { v[j] = in[row * D_MODEL + lane + j * 32]; s2 += v[j] * v[j]; }
    s2 = warpSum(s2);
    float n = sqrtf(s2 + 1e-15f);
    n = fminf(fmaxf(n, 1e-8f), 5.0f);
    float coef = tanhf(SQRT_C * n) / (SQRT_C * n);
    float rn = sqrtf(coef * coef * s2 + 1e-15f);
    float scale = (rn > MAX_NORM) ? (MAX_NORM / rn) : 1.f;
    #pragma unroll
    for (int j = 0; j < 12; j++) {
        float r = coef * v[j] * scale;
        out[row * D_MODEL + lane + j * 32] = r;
        if (outh) outh[row * D_MODEL + lane + j * 32] = __float2bfloat16(r);
    }
}

__global__ void k_logmap_rows(const float* __restrict__ in, float* __restrict__ out,
                              int nrows) {
    int row = blockIdx.x * ROWS_PER_BLK + (threadIdx.x >> 5);
    if (row >= nrows) return;
    int lane = threadIdx.x & 31;
    float v[12]; float s2 = 0.f;
    #pragma unroll
    for (int j = 0; j < 12; j++) { v[j] = in[row * D_MODEL + lane + j * 32]; s2 += v[j] * v[j]; }
    s2 = warpSum(s2);
    float n = sqrtf(s2 + 1e-15f);
    n = fminf(fmaxf(n, 1e-8f), MAX_NORM);
    float coef = atanhf(fminf(SQRT_C * n, 0.95f)) / (SQRT_C * n);
    #pragma unroll
    for (int j = 0; j < 12; j++) out[row * D_MODEL + lane + j * 32] = coef * v[j];
}

__global__ void k_mobius(const float* __restrict__ h, const float* __restrict__ mx,
                         const float* __restrict__ hb, float* __restrict__ out) {
    int row = blockIdx.x * ROWS_PER_BLK + (threadIdx.x >> 5);
    if (row >= NTOK) return;
    int lane = threadIdx.x & 31;
    float hv[12], mv[12], bv[12];
    float sh2 = 0.f, smx2 = 0.f, y2 = 0.f;
    #pragma unroll
    for (int j = 0; j < 12; j++) {
        int e = lane + j * 32;
        hv[j] = h[row * D_MODEL + e]; mv[j] = mx[row * D_MODEL + e]; bv[j] = hb[e];
        sh2 += hv[j] * hv[j]; smx2 += mv[j] * mv[j]; y2 += bv[j] * bv[j];
    }
    sh2 = warpSum(sh2); smx2 = warpSum(smx2); y2 = warpSum(y2);
    float xn  = fmaxf(sqrtf(sh2 + 1e-15f), 1e-8f);
    float mxn = fmaxf(sqrtf(smx2 + 1e-15f), 1e-8f);
    float tt = tanhf(mxn / xn * atanhf(fminf(SQRT_C * xn, 1.f - 1e-5f)));
    float c1 = tt / (mxn * SQRT_C);
    float xy = 0.f;
    #pragma unroll
    for (int j = 0; j < 12; j++) xy += c1 * mv[j] * bv[j];
    xy = warpSum(xy);
    float x2 = c1 * c1 * smx2;
    float alpha = 1.f + 2.f * C_CURV * xy + C_CURV * y2;
    float beta_ = 1.f - C_CURV * x2;
    float den = fmaxf(1.f + 2.f * C_CURV * xy + C_CURV * C_CURV * x2 * y2, 1e-15f);
    float rden = 1.f / den;
    #pragma unroll
    for (int j = 0; j < 12; j++)
        out[row * D_MODEL + lane + j * 32] = (alpha * c1 * mv[j] + beta_ * bv[j]) * rden;
}

__global__ void k_resid_hyp_ln(const float* __restrict__ hidden,
                               float* __restrict__ resid,
                               const float* __restrict__ gamma,
                               const float* __restrict__ beta,
                               __nv_bfloat16* __restrict__ outh,
                               float* __restrict__ outf, int doAdd) {
    int row = blockIdx.x * ROWS_PER_BLK + (threadIdx.x >> 5);
    if (row >= NTOK) return;
    int lane = threadIdx.x & 31;
    float v[12]; float s2 = 0.f;
    #pragma unroll
    for (int j = 0; j < 12; j++) {
        int e = lane + j * 32;
        float x = hidden[row * D_MODEL + e];
        if (doAdd) x += resid[row * D_MODEL + e];
        resid[row * D_MODEL + e] = x;
        v[j] = x; s2 += x * x;
    }
    s2 = warpSum(s2);
    float n = sqrtf(s2 + 1e-15f);
    n = fminf(fmaxf(n, 1e-8f), MAX_NORM);
    float coef = atanhf(fminf(SQRT_C * n, 0.95f)) / (SQRT_C * n);
    float mean = 0.f;
    #pragma unroll
    for (int j = 0; j < 12; j++) { v[j] *= coef; mean += v[j]; }
    mean = warpSum(mean) * (1.f / D_MODEL);
    float var = 0.f;
    #pragma unroll
    for (int j = 0; j < 12; j++) { v[j] -= mean; var += v[j] * v[j]; }
    var = warpSum(var) * (1.f / (D_MODEL - 1));
    float rstd = 1.f / (sqrtf(var) + 1e-5f);
    float su2 = 0.f;
    #pragma unroll
    for (int j = 0; j < 12; j++) {
        int e = lane + j * 32;
        v[j] = v[j] * rstd * gamma[e] + beta[e];
        su2 += v[j] * v[j];
    }
    su2 = warpSum(su2);
    float nu = sqrtf(su2 + 1e-15f);
    nu = fminf(fmaxf(nu, 1e-8f), 5.0f);
    float ec = tanhf(SQRT_C * nu) / (SQRT_C * nu);
    float rn = sqrtf(ec * ec * su2 + 1e-15f);
    float scale = (rn > MAX_NORM) ? (MAX_NORM / rn) : 1.f;
    #pragma unroll
    for (int j = 0; j < 12; j++) {
        float r = ec * v[j] * scale;
        if (outh) outh[row * D_MODEL + lane + j * 32] = __float2bfloat16(r);
        if (outf) outf[row * D_MODEL + lane + j * 32] = r;
    }
}

__global__ void k_posemb(const float* __restrict__ in, const float* __restrict__ pos,
                         float* __restrict__ out) {
    int row = blockIdx.x * ROWS_PER_BLK + (threadIdx.x >> 5);
    if (row >= NTOK) return;
    int lane = threadIdx.x & 31;
    int t = row % L_TOK;
    float v[12]; float s2 = 0.f;
    #pragma unroll
    for (int j = 0; j < 12; j++) { v[j] = in[row * D_MODEL + lane + j * 32]; s2 += v[j] * v[j]; }
    s2 = warpSum(s2);
    float n = sqrtf(s2 + 1e-15f);
    n = fminf(fmaxf(n, 1e-8f), MAX_NORM);
    float coef = atanhf(fminf(SQRT_C * n, 0.95f)) / (SQRT_C * n);
    float su2 = 0.f;
    #pragma unroll
    for (int j = 0; j < 12; j++) {
        int e = lane + j * 32;
        v[j] = coef * v[j] + pos[t * D_MODEL + e];
        su2 += v[j] * v[j];
    }
    su2 = warpSum(su2);
    float nu = sqrtf(su2 + 1e-15f);
    nu = fminf(fmaxf(nu, 1e-8f), 5.0f);
    float ec = tanhf(SQRT_C * nu) / (SQRT_C * nu);
    float rn = sqrtf(ec * ec * su2 + 1e-15f);
    float scale = (rn > MAX_NORM) ? (MAX_NORM / rn) : 1.f;
    #pragma unroll
    for (int j = 0; j < 12; j++) out[row * D_MODEL + lane + j * 32] = ec * v[j] * scale;
}

// ---------------- mean pool over tokens -------------------------------------
__global__ void k_pool(const float* __restrict__ in, float* __restrict__ out) {
    int b = blockIdx.x, e = threadIdx.x;
    float s = 0.f;
    for (int t = 0; t < L_TOK; t++) s += in[(b * L_TOK + t) * D_MODEL + e];
    out[b * D_MODEL + e] = s * (1.f / L_TOK);
}

// ---------------- hyperbolic distance classifier ----------------------------
__global__ void k_classifier(const float* __restrict__ pooled,
                             const float* __restrict__ protos,
                             float* __restrict__ out) {
    int warp = (blockIdx.x * blockDim.x + threadIdx.x) >> 5;
    int lane = threadIdx.x & 31;
    if (warp >= B_SZ * N_CLASSES) return;
    int b = warp / N_CLASSES, c = warp % N_CLASSES;
    float s_ab = 0.f, s_aa = 0.f, s_bb = 0.f;
    for (int e = lane; e < D_MODEL; e += 32) {
        float pa = pooled[b * D_MODEL + e];
        float pr = protos[c * D_MODEL + e];
        s_ab += pa * pr; s_aa += pa * pa; s_bb += pr * pr;
    }
    #pragma unroll
    for (int o = 16; o; o >>= 1) {
        s_ab += __shfl_down_sync(0xffffffffu, s_ab, o);
        s_aa += __shfl_down_sync(0xffffffffu, s_aa, o);
        s_bb += __shfl_down_sync(0xffffffffu, s_bb, o);
    }
    if (lane == 0) {
        float xy = -s_ab;
        float x2 = s_aa, y2 = s_bb;
        float alpha = 1.f + 2.f * C_CURV * xy + C_CURV * y2;
        float beta_ = 1.f - C_CURV * x2;
        float num2 = alpha * alpha * x2 + 2.f * alpha * beta_ * xy + beta_ * beta_ * y2;
        float den = fmaxf(1.f + 2.f * C_CURV * xy + C_CURV * C_CURV * x2 * y2, 1e-15f);
        float nrm = sqrtf(fmaxf(num2, 0.f) / (den * den) + 1e-15f);
        float dn = fminf(SQRT_C * nrm, 1.f - 1e-5f);
        out[b * N_CLASSES + c] = -(2.f / SQRT_C) * atanhf(dn);
    }
}

// ---------------- host orchestration ----------------------------------------
static void f2h(const float* src, __nv_bfloat16* dst, int n) {
    int n4 = n / 4;  // all weight sizes are multiples of 4
    k_f2h4<<<(n4 + 255) / 256, 256>>>(src, dst, n4);
}
static void gemm(const __nv_bfloat16* A, const __nv_bfloat16* W, const float* bias,
                 float* C, int N, int K) {
    dim3 grid(N / 64, NTOK_PAD / 64);
    if (bias) k_gemm_bf<true, false><<<grid, 128>>>(A, W, bias, C, NTOK_PAD, N, K);
    else      k_gemm_bf<false, false><<<grid, 128>>>(A, W, nullptr, C, NTOK_PAD, N, K);
}
static void gemm_ng(const __nv_bfloat16* A, const __nv_bfloat16* W, float* C,
                    int N, int K) {
    dim3 grid((N + 63) / 64, NTOK_PAD / 64);
    k_gemm_bf<false, true><<<grid, 128>>>(A, W, nullptr, C, NTOK_PAD, N, K);
}

#define ROW_GRID ((NTOK + ROWS_PER_BLK - 1) / ROWS_PER_BLK)

extern "C" void kernel_launch(void* const* d_in, const int* in_sizes, int n_in,
                              void* d_out, int out_size) {
    const float* x        = (const float*)d_in[0];
    const float* patch_w  = (const float*)d_in[1];
    const float* patch_b  = (const float*)d_in[2];
    const float* hyp_w    = (const float*)d_in[3];
    const float* hyp_b    = (const float*)d_in[4];
    const float* pe_gamma = (const float*)d_in[5];
    const float* pe_beta  = (const float*)d_in[6];
    const float* pos_emb  = (const float*)d_in[7];
    const float* in_proj  = (const float*)d_in[8];
    const float* conv_w   = (const float*)d_in[9];
    const float* conv_b   = (const float*)d_in[10];
    const float* x_proj   = (const float*)d_in[11];
    const float* dt_w     = (const float*)d_in[12];
    const float* dt_b     = (const float*)d_in[13];
    const float* A_log    = (const float*)d_in[14];
    const float* Dp       = (const float*)d_in[15];
    const float* out_proj = (const float*)d_in[16];
    const float* gamma    = (const float*)d_in[17];
    const float* beta     = (const float*)d_in[18];
    const float* gamma_f  = (const float*)d_in[19];
    const float* beta_f   = (const float*)d_in[20];
    const float* protos   = (const float*)d_in[21];
    float* out = (float*)d_out;

    float *hidden, *resid, *tmp, *xz, *dbl, *dtb_, *pool;
    cudaGetSymbolAddress((void**)&hidden,  g_hidden);
    cudaGetSymbolAddress((void**)&resid,   g_resid);
    cudaGetSymbolAddress((void**)&tmp,     g_tmp);
    cudaGetSymbolAddress((void**)&xz,      g_xz);
    cudaGetSymbolAddress((void**)&dbl,     g_dbl);
    cudaGetSymbolAddress((void**)&dtb_,    g_dt);
    cudaGetSymbolAddress((void**)&pool,    g_pool);
    __nv_bfloat16 *h_patches, *h_emb, *h_hn, *h_u, *h_y;
    __nv_bfloat16 *h_patch_w, *h_hyp_w, *h_in_w, *h_xp_w, *h_out_w;
    cudaGetSymbolAddress((void**)&h_patches, gh_patches);
    cudaGetSymbolAddress((void**)&h_emb,     gh_emb);
    cudaGetSymbolAddress((void**)&h_hn,      gh_hn);
    cudaGetSymbolAddress((void**)&h_u,       gh_u);
    cudaGetSymbolAddress((void**)&h_y,       gh_y);
    cudaGetSymbolAddress((void**)&h_patch_w, gh_patch_w);
    cudaGetSymbolAddress((void**)&h_hyp_w,   gh_hyp_w);
    cudaGetSymbolAddress((void**)&h_in_w,    gh_in_w);
    cudaGetSymbolAddress((void**)&h_xp_w,    gh_xp_w);
    cudaGetSymbolAddress((void**)&h_out_w,   gh_out_w);

    // weight conversion (every launch; deterministic)
    f2h(patch_w,  h_patch_w, D_MODEL * 768);
    f2h(hyp_w,    h_hyp_w,   D_MODEL * D_MODEL);
    f2h(in_proj,  h_in_w,    DEPTH * 2 * D_INNER * D_MODEL);
    f2h(x_proj,   h_xp_w,    DEPTH * XPROJ_OUT * D_INNER);
    f2h(out_proj, h_out_w,   DEPTH * D_MODEL * D_INNER);

    // patch embed -> tokens
    k_im2col<<<(NTOK * 768 + 255) / 256, 256>>>(x);
    gemm(h_patches, h_patch_w, patch_b, hidden, D_MODEL, 768);
    // hyperbolic embedding
    k_expmap_rows<<<ROW_GRID, 256>>>(hidden, hidden, h_emb, NTOK);
    gemm(h_emb, h_hyp_w, nullptr, tmp, D_MODEL, D_MODEL);
    k_mobius<<<ROW_GRID, 256>>>(hidden, tmp, hyp_b, hidden);
    k_resid_hyp_ln<<<ROW_GRID, 256>>>(hidden, tmp, pe_gamma, pe_beta,
                                      nullptr, hidden, 0);
    k_posemb<<<ROW_GRID, 256>>>(hidden, pos_emb, hidden);

    for (int i = 0; i < DEPTH; i++) {
        k_resid_hyp_ln<<<ROW_GRID, 256>>>(hidden, resid,
                                          gamma + i * D_MODEL, beta + i * D_MODEL,
                                          h_hn, nullptr, i > 0);
        gemm(h_hn, h_in_w + (size_t)i * 2 * D_INNER * D_MODEL, nullptr, xz,
             2 * D_INNER, D_MODEL);
        k_conv_silu<<<(NTOK * D_INNER + 255) / 256, 256>>>(
            xz, conv_w + i * D_INNER * D_CONV, conv_b + i * D_INNER);
        gemm_ng(h_u, h_xp_w + (size_t)i * XPROJ_OUT * D_INNER, dbl,
                XPROJ_OUT, D_INNER);
        k_dtproj<<<(NTOK * D_INNER + 255) / 256, 256>>>(
            dbl, dt_w + (size_t)i * D_INNER * DT_RANK, dt_b + i * D_INNER, dtb_);
        k_scan<<<dim3(D_INNER / 32, B_SZ), 512>>>(
            dtb_, dbl, xz, A_log + (size_t)i * D_INNER * D_STATE, Dp + i * D_INNER);
        gemm(h_y, h_out_w + (size_t)i * D_MODEL * D_INNER, nullptr, hidden,
             D_MODEL, D_INNER);
    }

    // final residual + LN + pool + classify
    k_resid_hyp_ln<<<ROW_GRID, 256>>>(hidden, resid, gamma_f, beta_f,
                                      nullptr, tmp, 1);
    k_logmap_rows<<<ROW_GRID, 256>>>(tmp, tmp, NTOK);
    k_pool<<<B_SZ, D_MODEL>>>(tmp, pool);
    k_expmap_rows<<<(B_SZ + ROWS_PER_BLK - 1) / ROWS_PER_BLK, 256>>>(
        pool, pool, nullptr, B_SZ);
    k_classifier<<<(B_SZ * N_CLASSES * 32 + 255) / 256, 256>>>(pool, protos, out);
}